// round 4
// baseline (speedup 1.0000x reference)
#include <cuda_runtime.h>

#define BB 2
#define SS 2048
#define DD 2048
#define HH 8
#define DKK 256
#define SCALING 0.0625f
#define NEGV (-1e9f)

// Scratch (device globals; no allocation allowed)
__device__ float g_Q[(size_t)BB * SS * DD];
__device__ float g_K[(size_t)BB * SS * DD];
__device__ float g_V[(size_t)BB * SS * DD];
__device__ float g_score[BB * HH * SS];
__device__ float g_pool[BB * DD];

// ---------------------------------------------------------------------------
// C[m,n] = sum_k A[m,k] * W[n,k] + bias[n]   (NT GEMM, both K-major)
// 128x128 block tile, BK=8, 256 threads, 8x8 micro-tile (split 4+4).
// ---------------------------------------------------------------------------
__global__ void __launch_bounds__(256) gemm128_nt_bias(
    const float* __restrict__ A, const float* __restrict__ W,
    const float* __restrict__ bias, float* __restrict__ C,
    int M, int N, int K)
{
    __shared__ float As[8][128];
    __shared__ float Ws[8][128];
    const int bm = blockIdx.y * 128;
    const int bn = blockIdx.x * 128;
    const int tid = threadIdx.x;
    const int tx = tid & 15, ty = tid >> 4;
    const int lr = tid >> 1;            // 0..127 row of tile
    const int lc = (tid & 1) * 4;       // 0 or 4 (k offset)

    float acc[8][8];
#pragma unroll
    for (int i = 0; i < 8; i++)
#pragma unroll
        for (int j = 0; j < 8; j++) acc[i][j] = 0.f;

    for (int k0 = 0; k0 < K; k0 += 8) {
        float4 a = *reinterpret_cast<const float4*>(A + (size_t)(bm + lr) * K + k0 + lc);
        float4 w = *reinterpret_cast<const float4*>(W + (size_t)(bn + lr) * K + k0 + lc);
        As[lc + 0][lr] = a.x; As[lc + 1][lr] = a.y; As[lc + 2][lr] = a.z; As[lc + 3][lr] = a.w;
        Ws[lc + 0][lr] = w.x; Ws[lc + 1][lr] = w.y; Ws[lc + 2][lr] = w.z; Ws[lc + 3][lr] = w.w;
        __syncthreads();
#pragma unroll
        for (int k = 0; k < 8; k++) {
            float4 a0 = *reinterpret_cast<const float4*>(&As[k][ty * 4]);
            float4 a1 = *reinterpret_cast<const float4*>(&As[k][64 + ty * 4]);
            float4 b0 = *reinterpret_cast<const float4*>(&Ws[k][tx * 4]);
            float4 b1 = *reinterpret_cast<const float4*>(&Ws[k][64 + tx * 4]);
            float am[8] = {a0.x, a0.y, a0.z, a0.w, a1.x, a1.y, a1.z, a1.w};
            float wn[8] = {b0.x, b0.y, b0.z, b0.w, b1.x, b1.y, b1.z, b1.w};
#pragma unroll
            for (int i = 0; i < 8; i++)
#pragma unroll
                for (int j = 0; j < 8; j++) acc[i][j] += am[i] * wn[j];
        }
        __syncthreads();
    }
#pragma unroll
    for (int i = 0; i < 8; i++) {
        int m = bm + ((i < 4) ? (ty * 4 + i) : (64 + ty * 4 + i - 4));
#pragma unroll
        for (int j = 0; j < 8; j++) {
            int n = bn + ((j < 4) ? (tx * 4 + j) : (64 + tx * 4 + j - 4));
            C[(size_t)m * N + n] = acc[i][j] + bias[n];
        }
    }
}

// ---------------------------------------------------------------------------
// score[b,h,i] = SCALING * ( sum_j leaky_relu(q_i . k_j, 0.1) * Wa[j] + ba )
// One block per (b, h, 64-row i-tile). j streamed in 64-tiles, dk in 16-tiles.
// Never materializes the SxS matrix.
// ---------------------------------------------------------------------------
__global__ void __launch_bounds__(256) score_kernel(
    const float* __restrict__ Q, const float* __restrict__ Kb,
    const float* __restrict__ Wa, const float* __restrict__ ba,
    float* __restrict__ score)
{
    const int b = blockIdx.z, h = blockIdx.y;
    const int i0 = blockIdx.x * 64;
    const float* Qh = Q + (size_t)b * SS * DD + h * DKK;
    const float* Kh = Kb + (size_t)b * SS * DD + h * DKK;

    __shared__ float Qs[16][65];
    __shared__ float Ks[16][65];

    const int tid = threadIdx.x;
    const int tx = tid & 15, ty = tid >> 4;
    const int lr = tid >> 2;           // 0..63
    const int lc = (tid & 3) * 4;      // 0,4,8,12

    float racc[4] = {0.f, 0.f, 0.f, 0.f};

    for (int j0 = 0; j0 < SS; j0 += 64) {
        float acc[4][4];
#pragma unroll
        for (int i = 0; i < 4; i++)
#pragma unroll
            for (int j = 0; j < 4; j++) acc[i][j] = 0.f;

        for (int dk0 = 0; dk0 < DKK; dk0 += 16) {
            float4 a = *reinterpret_cast<const float4*>(Qh + (size_t)(i0 + lr) * DD + dk0 + lc);
            float4 c = *reinterpret_cast<const float4*>(Kh + (size_t)(j0 + lr) * DD + dk0 + lc);
            Qs[lc + 0][lr] = a.x; Qs[lc + 1][lr] = a.y; Qs[lc + 2][lr] = a.z; Qs[lc + 3][lr] = a.w;
            Ks[lc + 0][lr] = c.x; Ks[lc + 1][lr] = c.y; Ks[lc + 2][lr] = c.z; Ks[lc + 3][lr] = c.w;
            __syncthreads();
#pragma unroll
            for (int k = 0; k < 16; k++) {
                float am[4], wn[4];
#pragma unroll
                for (int i = 0; i < 4; i++) am[i] = Qs[k][ty * 4 + i];
#pragma unroll
                for (int j = 0; j < 4; j++) wn[j] = Ks[k][tx * 4 + j];
#pragma unroll
                for (int i = 0; i < 4; i++)
#pragma unroll
                    for (int j = 0; j < 4; j++) acc[i][j] += am[i] * wn[j];
            }
            __syncthreads();
        }
        // epilogue: leaky_relu then weight by Wa[j], fold into per-i accumulator
#pragma unroll
        for (int j = 0; j < 4; j++) {
            float waj = Wa[j0 + tx * 4 + j];
#pragma unroll
            for (int i = 0; i < 4; i++) {
                float e = acc[i][j];
                e = (e >= 0.f) ? e : 0.1f * e;
                racc[i] += e * waj;
            }
        }
    }
    // reduce over the 16 tx lanes (each group of 16 lanes shares the same ty)
#pragma unroll
    for (int i = 0; i < 4; i++) {
        float v = racc[i];
#pragma unroll
        for (int o = 8; o >= 1; o >>= 1) v += __shfl_xor_sync(0xffffffffu, v, o);
        if (tx == 0)
            score[((size_t)b * HH + h) * SS + i0 + ty * 4 + i] = SCALING * (v + ba[0]);
    }
}

// ---------------------------------------------------------------------------
// Masked softmax over the token axis, in-place on score rows of length S.
// ---------------------------------------------------------------------------
__global__ void __launch_bounds__(256) softmax_kernel(float* __restrict__ score,
                                                      const int* __restrict__ mask)
{
    float* row = score + (size_t)blockIdx.x * SS;
    __shared__ float red[256];
    const int tid = threadIdx.x;

    float mx = -3.4e38f;
    for (int i = tid; i < SS; i += 256) {
        float v = (mask[i] != 0) ? NEGV : row[i];
        row[i] = v;
        mx = fmaxf(mx, v);
    }
    red[tid] = mx; __syncthreads();
    for (int o = 128; o >= 1; o >>= 1) {
        if (tid < o) red[tid] = fmaxf(red[tid], red[tid + o]);
        __syncthreads();
    }
    mx = red[0];
    __syncthreads();

    float sum = 0.f;
    for (int i = tid; i < SS; i += 256) {
        float e = __expf(row[i] - mx);
        row[i] = e;
        sum += e;
    }
    red[tid] = sum; __syncthreads();
    for (int o = 128; o >= 1; o >>= 1) {
        if (tid < o) red[tid] += red[tid + o];
        __syncthreads();
    }
    float inv = 1.f / red[0];
    for (int i = tid; i < SS; i += 256) row[i] *= inv;
}

__global__ void zero_kernel(float* __restrict__ p)
{
    int i = blockIdx.x * blockDim.x + threadIdx.x;
    if (i < BB * DD) p[i] = 0.f;
}

// pooled[b, h*DK + d] = sum_i attn[b,h,i] * V[b, i, h*DK + d]
__global__ void __launch_bounds__(256) pool_kernel(
    const float* __restrict__ V, const float* __restrict__ attn,
    float* __restrict__ pooled)
{
    const int b = blockIdx.z, h = blockIdx.y;
    const int d = threadIdx.x;                      // 0..255 (= DK)
    const int i0 = blockIdx.x * 128;
    const float* Vh = V + (size_t)b * SS * DD + h * DKK + d;
    const float* a = attn + ((size_t)b * HH + h) * SS;
    float acc = 0.f;
#pragma unroll 4
    for (int i = i0; i < i0 + 128; i++) acc += a[i] * Vh[(size_t)i * DD];
    atomicAdd(&pooled[(size_t)b * DD + h * DKK + d], acc);
}

// out[b,n] = tanh( sum_k pooled[b,k] * Wp[n,k] + bp[n] )  -- one warp per (b,n)
__global__ void __launch_bounds__(256) final_kernel(
    const float* __restrict__ pooled, const float* __restrict__ Wp,
    const float* __restrict__ bp, float* __restrict__ out)
{
    const int warp = (blockIdx.x * blockDim.x + threadIdx.x) >> 5;
    const int lane = threadIdx.x & 31;
    const int b = warp >> 11;           // / 2048
    const int n = warp & 2047;
    const float* wrow = Wp + (size_t)n * DD;
    const float* prow = pooled + (size_t)b * DD;
    float acc = 0.f;
    for (int k = lane * 4; k < DD; k += 128) {
        float4 w = *reinterpret_cast<const float4*>(wrow + k);
        float4 p = *reinterpret_cast<const float4*>(prow + k);
        acc += w.x * p.x + w.y * p.y + w.z * p.z + w.w * p.w;
    }
#pragma unroll
    for (int o = 16; o >= 1; o >>= 1) acc += __shfl_xor_sync(0xffffffffu, acc, o);
    if (lane == 0) out[(size_t)b * DD + n] = tanhf(acc + bp[n]);
}

extern "C" void kernel_launch(void* const* d_in, const int* in_sizes, int n_in,
                              void* d_out, int out_size)
{
    const float* x    = (const float*)d_in[0];
    const int*   xmsk = (const int*)  d_in[1];
    const float* Wq   = (const float*)d_in[2];
    const float* bq   = (const float*)d_in[3];
    const float* Wk   = (const float*)d_in[4];
    const float* bk   = (const float*)d_in[5];
    const float* Wv   = (const float*)d_in[6];
    const float* bv   = (const float*)d_in[7];
    const float* Wa   = (const float*)d_in[8];
    const float* ba   = (const float*)d_in[9];
    const float* Wp   = (const float*)d_in[10];
    const float* bp   = (const float*)d_in[11];
    float* out = (float*)d_out;

    float *Qp, *Kp, *Vp, *Sp, *Pp;
    cudaGetSymbolAddress((void**)&Qp, g_Q);
    cudaGetSymbolAddress((void**)&Kp, g_K);
    cudaGetSymbolAddress((void**)&Vp, g_V);
    cudaGetSymbolAddress((void**)&Sp, g_score);
    cudaGetSymbolAddress((void**)&Pp, g_pool);

    dim3 gq(DD / 128, (BB * SS) / 128);         // (16, 32)
    gemm128_nt_bias<<<gq, 256>>>(x, Wq, bq, Qp, BB * SS, DD, DD);
    gemm128_nt_bias<<<gq, 256>>>(x, Wk, bk, Kp, BB * SS, DD, DD);
    gemm128_nt_bias<<<gq, 256>>>(x, Wv, bv, Vp, BB * SS, DD, DD);

    score_kernel<<<dim3(SS / 64, HH, BB), 256>>>(Qp, Kp, Wa, ba, Sp);
    softmax_kernel<<<BB * HH, 256>>>(Sp, xmsk);

    zero_kernel<<<(BB * DD + 255) / 256, 256>>>(Pp);
    pool_kernel<<<dim3(SS / 128, HH, BB), 256>>>(Vp, Sp, Pp);
    final_kernel<<<(BB * DD) / 8, 256>>>(Pp, Wp, bp, out);
}

// round 5
// speedup vs baseline: 3.6556x; 3.6556x over previous
#include <cuda_runtime.h>
#include <cstdint>

#define BB 2
#define SS 2048
#define DD 2048
#define HH 8
#define DKK 256
#define SCALING 0.0625f
#define NEGV (-1e9f)

// Scratch (device globals; no allocation allowed)
__device__ float g_Q[(size_t)BB * SS * DD];
__device__ float g_K[(size_t)BB * SS * DD];
__device__ float g_V[(size_t)BB * SS * DD];
__device__ float g_score[BB * HH * SS];
__device__ float g_pool[BB * DD];

// ---------------------------------------------------------------------------
// helpers: tf32 convert, mma, cp.async
// ---------------------------------------------------------------------------
__device__ __forceinline__ uint32_t f2tf32(float x) {
    uint32_t u;
    asm("cvt.rna.tf32.f32 %0, %1;" : "=r"(u) : "f"(x));
    return u;
}

#define MMA_TF32(d0,d1,d2,d3,a0,a1,a2,a3,b0,b1)                               \
    asm volatile("mma.sync.aligned.m16n8k8.row.col.f32.tf32.tf32.f32 "        \
                 "{%0,%1,%2,%3},{%4,%5,%6,%7},{%8,%9},{%0,%1,%2,%3};"         \
                 : "+f"(d0), "+f"(d1), "+f"(d2), "+f"(d3)                     \
                 : "r"(a0), "r"(a1), "r"(a2), "r"(a3), "r"(b0), "r"(b1))

__device__ __forceinline__ void cp16(void* smem, const void* gmem) {
    uint32_t sa = (uint32_t)__cvta_generic_to_shared(smem);
    asm volatile("cp.async.cg.shared.global [%0], [%1], 16;" :: "r"(sa), "l"(gmem));
}
__device__ __forceinline__ void cp_commit() { asm volatile("cp.async.commit_group;"); }
__device__ __forceinline__ void cp_wait1() { asm volatile("cp.async.wait_group 1;"); }
__device__ __forceinline__ void cp_wait0() { asm volatile("cp.async.wait_group 0;"); }

// ---------------------------------------------------------------------------
// Tensor-core NT GEMM: C[m,n] = sum_k A[m,k]*W[n,k] + bias[n]
// 128x128 block tile, BK=16, 256 threads (8 warps @ 64x32), tf32 mma.
// smem [row][k] with stride 20 -> conflict-free fragment gathers.
// ---------------------------------------------------------------------------
__global__ void __launch_bounds__(256) gemm_tc_nt_bias(
    const float* __restrict__ A, const float* __restrict__ W,
    const float* __restrict__ bias, float* __restrict__ C,
    int M, int N, int K)
{
    __shared__ float As[2][128][20];
    __shared__ float Bs[2][128][20];

    const int bm = blockIdx.y * 128;
    const int bn = blockIdx.x * 128;
    const int tid = threadIdx.x;
    const int warp = tid >> 5, lane = tid & 31;
    const int wm = warp & 1;          // 0..1 : 64-row slice
    const int wn = warp >> 1;         // 0..3 : 32-col slice
    const int g = lane >> 2, c = lane & 3;

    // cp.async mapping: 128 rows x 16 floats = 512 float4; 2 per thread per tile
    const int lrow0 = tid >> 2, lc4 = (tid & 3) * 4;         // chunk 0: rows 0..63
    const int lrow1 = lrow0 + 64;                             // chunk 1: rows 64..127

    float acc[4][4][4];
#pragma unroll
    for (int i = 0; i < 4; i++)
#pragma unroll
        for (int j = 0; j < 4; j++)
#pragma unroll
            for (int r = 0; r < 4; r++) acc[i][j][r] = 0.f;

    const int nk = K >> 4;

    // prefetch stage 0
    {
        cp16(&As[0][lrow0][lc4], A + (size_t)(bm + lrow0) * K + lc4);
        cp16(&As[0][lrow1][lc4], A + (size_t)(bm + lrow1) * K + lc4);
        cp16(&Bs[0][lrow0][lc4], W + (size_t)(bn + lrow0) * K + lc4);
        cp16(&Bs[0][lrow1][lc4], W + (size_t)(bn + lrow1) * K + lc4);
        cp_commit();
    }

    for (int kt = 0; kt < nk; kt++) {
        if (kt + 1 < nk) {
            const int nb = (kt + 1) & 1;
            const int k0 = (kt + 1) << 4;
            cp16(&As[nb][lrow0][lc4], A + (size_t)(bm + lrow0) * K + k0 + lc4);
            cp16(&As[nb][lrow1][lc4], A + (size_t)(bm + lrow1) * K + k0 + lc4);
            cp16(&Bs[nb][lrow0][lc4], W + (size_t)(bn + lrow0) * K + k0 + lc4);
            cp16(&Bs[nb][lrow1][lc4], W + (size_t)(bn + lrow1) * K + k0 + lc4);
            cp_commit();
            cp_wait1();
        } else {
            cp_wait0();
        }
        __syncthreads();

        const int buf = kt & 1;
#pragma unroll
        for (int kk = 0; kk < 2; kk++) {
            const int k = kk * 8;
            uint32_t af[4][4], bf[4][2];
#pragma unroll
            for (int mt = 0; mt < 4; mt++) {
                const int r0 = wm * 64 + mt * 16 + g;
                af[mt][0] = f2tf32(As[buf][r0][k + c]);
                af[mt][1] = f2tf32(As[buf][r0 + 8][k + c]);
                af[mt][2] = f2tf32(As[buf][r0][k + c + 4]);
                af[mt][3] = f2tf32(As[buf][r0 + 8][k + c + 4]);
            }
#pragma unroll
            for (int nt = 0; nt < 4; nt++) {
                const int n0 = wn * 32 + nt * 8 + g;
                bf[nt][0] = f2tf32(Bs[buf][n0][k + c]);
                bf[nt][1] = f2tf32(Bs[buf][n0][k + c + 4]);
            }
#pragma unroll
            for (int mt = 0; mt < 4; mt++)
#pragma unroll
                for (int nt = 0; nt < 4; nt++)
                    MMA_TF32(acc[mt][nt][0], acc[mt][nt][1], acc[mt][nt][2], acc[mt][nt][3],
                             af[mt][0], af[mt][1], af[mt][2], af[mt][3],
                             bf[nt][0], bf[nt][1]);
        }
        __syncthreads();
    }

    // epilogue: + bias, store
#pragma unroll
    for (int mt = 0; mt < 4; mt++) {
        const int r = bm + wm * 64 + mt * 16 + g;
#pragma unroll
        for (int nt = 0; nt < 4; nt++) {
            const int col = bn + wn * 32 + nt * 8 + 2 * c;
            const float b0 = bias[col], b1 = bias[col + 1];
            float2 v0 = make_float2(acc[mt][nt][0] + b0, acc[mt][nt][1] + b1);
            float2 v1 = make_float2(acc[mt][nt][2] + b0, acc[mt][nt][3] + b1);
            *reinterpret_cast<float2*>(&C[(size_t)r * N + col]) = v0;
            *reinterpret_cast<float2*>(&C[(size_t)(r + 8) * N + col]) = v1;
        }
    }
}

// ---------------------------------------------------------------------------
// Tensor-core score kernel:
// score[b,h,i] = SCALING * ( sum_j leaky_relu(q_i.k_j, 0.1)*Wa[j] + ba )
// Block = (b,h, 128-row i-tile); j streamed in 128-tiles; K-dim = DK = 256.
// Same mma structure; fused leaky/Wa/row-sum epilogue per j-tile.
// ---------------------------------------------------------------------------
__global__ void __launch_bounds__(256) score_tc_kernel(
    const float* __restrict__ Q, const float* __restrict__ Kb,
    const float* __restrict__ Wa, const float* __restrict__ ba,
    float* __restrict__ score)
{
    __shared__ float As[2][128][20];
    __shared__ float Bs[2][128][20];
    __shared__ float red[4][128];

    const int b = blockIdx.z, h = blockIdx.y;
    const int i0 = blockIdx.x * 128;
    const float* Qh = Q + (size_t)b * SS * DD + (size_t)h * DKK;
    const float* Kh = Kb + (size_t)b * SS * DD + (size_t)h * DKK;

    const int tid = threadIdx.x;
    const int warp = tid >> 5, lane = tid & 31;
    const int wm = warp & 1, wn = warp >> 1;
    const int g = lane >> 2, c = lane & 3;
    const int lrow0 = tid >> 2, lc4 = (tid & 3) * 4;
    const int lrow1 = lrow0 + 64;

    float racc[4][2];
#pragma unroll
    for (int mt = 0; mt < 4; mt++) { racc[mt][0] = 0.f; racc[mt][1] = 0.f; }

    const int nk = DKK >> 4;   // 16 stages

    for (int j0 = 0; j0 < SS; j0 += 128) {
        float acc[4][4][4];
#pragma unroll
        for (int i = 0; i < 4; i++)
#pragma unroll
            for (int j = 0; j < 4; j++)
#pragma unroll
                for (int r = 0; r < 4; r++) acc[i][j][r] = 0.f;

        // prefetch stage 0
        cp16(&As[0][lrow0][lc4], Qh + (size_t)(i0 + lrow0) * DD + lc4);
        cp16(&As[0][lrow1][lc4], Qh + (size_t)(i0 + lrow1) * DD + lc4);
        cp16(&Bs[0][lrow0][lc4], Kh + (size_t)(j0 + lrow0) * DD + lc4);
        cp16(&Bs[0][lrow1][lc4], Kh + (size_t)(j0 + lrow1) * DD + lc4);
        cp_commit();

        for (int kt = 0; kt < nk; kt++) {
            if (kt + 1 < nk) {
                const int nb = (kt + 1) & 1;
                const int k0 = (kt + 1) << 4;
                cp16(&As[nb][lrow0][lc4], Qh + (size_t)(i0 + lrow0) * DD + k0 + lc4);
                cp16(&As[nb][lrow1][lc4], Qh + (size_t)(i0 + lrow1) * DD + k0 + lc4);
                cp16(&Bs[nb][lrow0][lc4], Kh + (size_t)(j0 + lrow0) * DD + k0 + lc4);
                cp16(&Bs[nb][lrow1][lc4], Kh + (size_t)(j0 + lrow1) * DD + k0 + lc4);
                cp_commit();
                cp_wait1();
            } else {
                cp_wait0();
            }
            __syncthreads();

            const int buf = kt & 1;
#pragma unroll
            for (int kk = 0; kk < 2; kk++) {
                const int k = kk * 8;
                uint32_t af[4][4], bf[4][2];
#pragma unroll
                for (int mt = 0; mt < 4; mt++) {
                    const int r0 = wm * 64 + mt * 16 + g;
                    af[mt][0] = f2tf32(As[buf][r0][k + c]);
                    af[mt][1] = f2tf32(As[buf][r0 + 8][k + c]);
                    af[mt][2] = f2tf32(As[buf][r0][k + c + 4]);
                    af[mt][3] = f2tf32(As[buf][r0 + 8][k + c + 4]);
                }
#pragma unroll
                for (int nt = 0; nt < 4; nt++) {
                    const int n0 = wn * 32 + nt * 8 + g;
                    bf[nt][0] = f2tf32(Bs[buf][n0][k + c]);
                    bf[nt][1] = f2tf32(Bs[buf][n0][k + c + 4]);
                }
#pragma unroll
                for (int mt = 0; mt < 4; mt++)
#pragma unroll
                    for (int nt = 0; nt < 4; nt++)
                        MMA_TF32(acc[mt][nt][0], acc[mt][nt][1], acc[mt][nt][2], acc[mt][nt][3],
                                 af[mt][0], af[mt][1], af[mt][2], af[mt][3],
                                 bf[nt][0], bf[nt][1]);
            }
            __syncthreads();
        }

        // fused epilogue: leaky_relu -> * Wa[j] -> fold into per-row accumulator
#pragma unroll
        for (int nt = 0; nt < 4; nt++) {
            const int colg = j0 + wn * 32 + nt * 8 + 2 * c;
            const float wa0 = Wa[colg], wa1 = Wa[colg + 1];
#pragma unroll
            for (int mt = 0; mt < 4; mt++) {
                float e0 = acc[mt][nt][0]; e0 = (e0 >= 0.f) ? e0 : 0.1f * e0;
                float e1 = acc[mt][nt][1]; e1 = (e1 >= 0.f) ? e1 : 0.1f * e1;
                float e2 = acc[mt][nt][2]; e2 = (e2 >= 0.f) ? e2 : 0.1f * e2;
                float e3 = acc[mt][nt][3]; e3 = (e3 >= 0.f) ? e3 : 0.1f * e3;
                racc[mt][0] += e0 * wa0 + e1 * wa1;
                racc[mt][1] += e2 * wa0 + e3 * wa1;
            }
        }
    }

    // reduce across the 4 "c" lanes of each quad (rows are per-g)
#pragma unroll
    for (int mt = 0; mt < 4; mt++) {
#pragma unroll
        for (int half = 0; half < 2; half++) {
            float v = racc[mt][half];
            v += __shfl_xor_sync(0xffffffffu, v, 1);
            v += __shfl_xor_sync(0xffffffffu, v, 2);
            racc[mt][half] = v;
        }
    }
    // cross-warp (wn) reduce via smem
    if (c == 0) {
#pragma unroll
        for (int mt = 0; mt < 4; mt++) {
            const int r0 = wm * 64 + mt * 16 + g;
            red[wn][r0] = racc[mt][0];
            red[wn][r0 + 8] = racc[mt][1];
        }
    }
    __syncthreads();
    if (tid < 128) {
        float s = red[0][tid] + red[1][tid] + red[2][tid] + red[3][tid];
        score[((size_t)b * HH + h) * SS + i0 + tid] = SCALING * (s + ba[0]);
    }
}

// ---------------------------------------------------------------------------
// Masked softmax over the token axis, in-place on score rows of length S.
// ---------------------------------------------------------------------------
__global__ void __launch_bounds__(256) softmax_kernel(float* __restrict__ score,
                                                      const int* __restrict__ mask)
{
    float* row = score + (size_t)blockIdx.x * SS;
    __shared__ float red[256];
    const int tid = threadIdx.x;

    float mx = -3.4e38f;
    for (int i = tid; i < SS; i += 256) {
        float v = (mask[i] != 0) ? NEGV : row[i];
        row[i] = v;
        mx = fmaxf(mx, v);
    }
    red[tid] = mx; __syncthreads();
    for (int o = 128; o >= 1; o >>= 1) {
        if (tid < o) red[tid] = fmaxf(red[tid], red[tid + o]);
        __syncthreads();
    }
    mx = red[0];
    __syncthreads();

    float sum = 0.f;
    for (int i = tid; i < SS; i += 256) {
        float e = __expf(row[i] - mx);
        row[i] = e;
        sum += e;
    }
    red[tid] = sum; __syncthreads();
    for (int o = 128; o >= 1; o >>= 1) {
        if (tid < o) red[tid] += red[tid + o];
        __syncthreads();
    }
    float inv = 1.f / red[0];
    for (int i = tid; i < SS; i += 256) row[i] *= inv;
}

__global__ void zero_kernel(float* __restrict__ p)
{
    int i = blockIdx.x * blockDim.x + threadIdx.x;
    if (i < BB * DD) p[i] = 0.f;
}

// pooled[b, h*DK + d] = sum_i attn[b,h,i] * V[b, i, h*DK + d]
__global__ void __launch_bounds__(256) pool_kernel(
    const float* __restrict__ V, const float* __restrict__ attn,
    float* __restrict__ pooled)
{
    const int b = blockIdx.z, h = blockIdx.y;
    const int d = threadIdx.x;
    const int i0 = blockIdx.x * 128;
    const float* Vh = V + (size_t)b * SS * DD + h * DKK + d;
    const float* a = attn + ((size_t)b * HH + h) * SS;
    float acc = 0.f;
#pragma unroll 4
    for (int i = i0; i < i0 + 128; i++) acc += a[i] * Vh[(size_t)i * DD];
    atomicAdd(&pooled[(size_t)b * DD + h * DKK + d], acc);
}

// out[b,n] = tanh( sum_k pooled[b,k] * Wp[n,k] + bp[n] )  -- one warp per (b,n)
__global__ void __launch_bounds__(256) final_kernel(
    const float* __restrict__ pooled, const float* __restrict__ Wp,
    const float* __restrict__ bp, float* __restrict__ out)
{
    const int warp = (blockIdx.x * blockDim.x + threadIdx.x) >> 5;
    const int lane = threadIdx.x & 31;
    const int b = warp >> 11;
    const int n = warp & 2047;
    const float* wrow = Wp + (size_t)n * DD;
    const float* prow = pooled + (size_t)b * DD;
    float acc = 0.f;
    for (int k = lane * 4; k < DD; k += 128) {
        float4 w = *reinterpret_cast<const float4*>(wrow + k);
        float4 p = *reinterpret_cast<const float4*>(prow + k);
        acc += w.x * p.x + w.y * p.y + w.z * p.z + w.w * p.w;
    }
#pragma unroll
    for (int o = 16; o >= 1; o >>= 1) acc += __shfl_xor_sync(0xffffffffu, acc, o);
    if (lane == 0) out[(size_t)b * DD + n] = tanhf(acc + bp[n]);
}

extern "C" void kernel_launch(void* const* d_in, const int* in_sizes, int n_in,
                              void* d_out, int out_size)
{
    const float* x    = (const float*)d_in[0];
    const int*   xmsk = (const int*)  d_in[1];
    const float* Wq   = (const float*)d_in[2];
    const float* bq   = (const float*)d_in[3];
    const float* Wk   = (const float*)d_in[4];
    const float* bk   = (const float*)d_in[5];
    const float* Wv   = (const float*)d_in[6];
    const float* bv   = (const float*)d_in[7];
    const float* Wa   = (const float*)d_in[8];
    const float* ba   = (const float*)d_in[9];
    const float* Wp   = (const float*)d_in[10];
    const float* bp   = (const float*)d_in[11];
    float* out = (float*)d_out;

    float *Qp, *Kp, *Vp, *Sp, *Pp;
    cudaGetSymbolAddress((void**)&Qp, g_Q);
    cudaGetSymbolAddress((void**)&Kp, g_K);
    cudaGetSymbolAddress((void**)&Vp, g_V);
    cudaGetSymbolAddress((void**)&Sp, g_score);
    cudaGetSymbolAddress((void**)&Pp, g_pool);

    dim3 gq(DD / 128, (BB * SS) / 128);         // (16, 32)
    gemm_tc_nt_bias<<<gq, 256>>>(x, Wq, bq, Qp, BB * SS, DD, DD);
    gemm_tc_nt_bias<<<gq, 256>>>(x, Wk, bk, Kp, BB * SS, DD, DD);
    gemm_tc_nt_bias<<<gq, 256>>>(x, Wv, bv, Vp, BB * SS, DD, DD);

    score_tc_kernel<<<dim3(SS / 128, HH, BB), 256>>>(Qp, Kp, Wa, ba, Sp);
    softmax_kernel<<<BB * HH, 256>>>(Sp, xmsk);

    zero_kernel<<<(BB * DD + 255) / 256, 256>>>(Pp);
    pool_kernel<<<dim3(SS / 128, HH, BB), 256>>>(Vp, Sp, Pp);
    final_kernel<<<(BB * DD) / 8, 256>>>(Pp, Wp, bp, out);
}